// round 3
// baseline (speedup 1.0000x reference)
#include <cuda_runtime.h>
#include <cuda_bf16.h>
#include <math.h>

// ---------------------------------------------------------------------------
// STTM: 4-layer transformer, w=192, C=128, NHEAD=4, hd=32
// feat layout: (w, n, C) row-major. Self: n in [0,256). fl: n<128, fr: n>=128.
// Rel-pos: project pos_enc (383 rows) once per layer; attention gathers by
// d = 191 - DSIGN*(i-j). Attention scores/AV now run on tf32 mma.sync.
// ---------------------------------------------------------------------------

#define W_ 192
#define CC 128

// ------------------------- device scratch ---------------------------------
__device__ float g_ln [W_*256*CC];
__device__ float g_ln2[W_*128*CC];
__device__ float g_qkv[W_*256*3*CC];
__device__ float g_vo [W_*256*CC];
__device__ float g_proj[2*383*256];

// ------------------------- tf32 helpers ------------------------------------
__device__ __forceinline__ float tf32r(float x) {
    unsigned y;
    asm("cvt.rna.tf32.f32 %0, %1;" : "=r"(y) : "f"(x));
    return __uint_as_float(y);
}

__device__ __forceinline__ void mma8(float4& d, const unsigned* a, unsigned b0, unsigned b1) {
    asm volatile(
        "mma.sync.aligned.m16n8k8.row.col.f32.tf32.tf32.f32 "
        "{%0,%1,%2,%3},{%4,%5,%6,%7},{%8,%9},{%0,%1,%2,%3};"
        : "+f"(d.x), "+f"(d.y), "+f"(d.z), "+f"(d.w)
        : "r"(a[0]), "r"(a[1]), "r"(a[2]), "r"(a[3]), "r"(b0), "r"(b1));
}

// ------------------------- build feat from inputs -------------------------
__global__ void build_feat(const float* __restrict__ L, const float* __restrict__ R,
                           float* __restrict__ feat)
{
    __shared__ float tile[32][33];
    int n = blockIdx.z;
    const float* src = (n < 128) ? L : R;
    int nn = n & 127;
    int h = nn >> 1, b = nn & 1;
    int i = blockIdx.x * 32 + threadIdx.x;
    int c = blockIdx.y * 32 + threadIdx.y;
    tile[threadIdx.y][threadIdx.x] = src[(((size_t)b * 128 + c) * 64 + h) * 192 + i];
    __syncthreads();
    int i2 = blockIdx.x * 32 + threadIdx.y;
    int c2 = blockIdx.y * 32 + threadIdx.x;
    feat[((size_t)i2 * 256 + n) * 128 + c2] = tile[threadIdx.x][threadIdx.y];
}

// ------------------------- LayerNorm: 1 warp per row, 4 rows/block ---------
__global__ void ln4_kernel(const float* __restrict__ x, int n0, int nW, int nF,
                           const float* __restrict__ g, const float* __restrict__ b,
                           float* __restrict__ y)
{
    int t = blockIdx.x * 4 + (threadIdx.x >> 5);
    int lane = threadIdx.x & 31;
    int row = (t / nW) * nF + n0 + (t % nW);
    float4 v = *(const float4*)(x + (size_t)row * 128 + lane * 4);
    float s  = v.x + v.y + v.z + v.w;
    float sq = v.x*v.x + v.y*v.y + v.z*v.z + v.w*v.w;
    #pragma unroll
    for (int o = 16; o > 0; o >>= 1) {
        s  += __shfl_xor_sync(0xffffffffu, s,  o);
        sq += __shfl_xor_sync(0xffffffffu, sq, o);
    }
    float mean = s * (1.f / 128.f);
    float var  = sq * (1.f / 128.f) - mean * mean;
    float inv = rsqrtf(var + 1e-5f);
    float4 gv = *(const float4*)(g + lane * 4);
    float4 bv = *(const float4*)(b + lane * 4);
    float4 o4;
    o4.x = (v.x - mean) * inv * gv.x + bv.x;
    o4.y = (v.y - mean) * inv * gv.y + bv.y;
    o4.z = (v.z - mean) * inv * gv.z + bv.z;
    o4.w = (v.w - mean) * inv * gv.w + bv.w;
    *(float4*)(y + (size_t)t * 128 + lane * 4) = o4;
}

// ------------------------- small SGEMM (64x64 tiles, bounds-checked) -------
__global__ void sgemm64(const float* __restrict__ A, int aN0, int aNW, int aNF,
                        const float* __restrict__ B, const float* __restrict__ bias,
                        float* __restrict__ C, int cN0, int cNW, int cNF, int cPitch,
                        int M, int N, int addRes)
{
    __shared__ float As[16][68];
    __shared__ float Bs[16][68];
    int tid = threadIdx.x;
    int tx = tid & 15, ty = tid >> 4;
    int rowBase = blockIdx.y * 64;
    int colBase = blockIdx.x * 64;

    float acc[4][4];
    #pragma unroll
    for (int i = 0; i < 4; i++)
        #pragma unroll
        for (int j = 0; j < 4; j++) acc[i][j] = 0.f;

    int lr = tid >> 2;
    int lc = (tid & 3) * 4;
    int ar = rowBase + lr;
    const float* aRowPtr = nullptr;
    if (ar < M) {
        int arow = (ar / aNW) * aNF + aN0 + (ar % aNW);
        aRowPtr = A + (size_t)arow * 128;
    }
    int bc = colBase + lr;
    const float* bRowPtr = (bc < N) ? (B + (size_t)bc * 128) : nullptr;

    for (int kt = 0; kt < 8; kt++) {
        int k0 = kt * 16 + lc;
        float4 av = aRowPtr ? *(const float4*)(aRowPtr + k0) : make_float4(0, 0, 0, 0);
        float4 bv = bRowPtr ? *(const float4*)(bRowPtr + k0) : make_float4(0, 0, 0, 0);
        As[lc + 0][lr] = av.x; As[lc + 1][lr] = av.y; As[lc + 2][lr] = av.z; As[lc + 3][lr] = av.w;
        Bs[lc + 0][lr] = bv.x; Bs[lc + 1][lr] = bv.y; Bs[lc + 2][lr] = bv.z; Bs[lc + 3][lr] = bv.w;
        __syncthreads();
        #pragma unroll
        for (int k = 0; k < 16; k++) {
            float a0 = As[k][ty * 4 + 0], a1 = As[k][ty * 4 + 1];
            float a2 = As[k][ty * 4 + 2], a3 = As[k][ty * 4 + 3];
            float b0 = Bs[k][tx * 4 + 0], b1 = Bs[k][tx * 4 + 1];
            float b2 = Bs[k][tx * 4 + 2], b3 = Bs[k][tx * 4 + 3];
            acc[0][0] = fmaf(a0, b0, acc[0][0]); acc[0][1] = fmaf(a0, b1, acc[0][1]);
            acc[0][2] = fmaf(a0, b2, acc[0][2]); acc[0][3] = fmaf(a0, b3, acc[0][3]);
            acc[1][0] = fmaf(a1, b0, acc[1][0]); acc[1][1] = fmaf(a1, b1, acc[1][1]);
            acc[1][2] = fmaf(a1, b2, acc[1][2]); acc[1][3] = fmaf(a1, b3, acc[1][3]);
            acc[2][0] = fmaf(a2, b0, acc[2][0]); acc[2][1] = fmaf(a2, b1, acc[2][1]);
            acc[2][2] = fmaf(a2, b2, acc[2][2]); acc[2][3] = fmaf(a2, b3, acc[2][3]);
            acc[3][0] = fmaf(a3, b0, acc[3][0]); acc[3][1] = fmaf(a3, b1, acc[3][1]);
            acc[3][2] = fmaf(a3, b2, acc[3][2]); acc[3][3] = fmaf(a3, b3, acc[3][3]);
        }
        __syncthreads();
    }

    #pragma unroll
    for (int mi = 0; mi < 4; mi++) {
        int r = rowBase + ty * 4 + mi;
        if (r >= M) continue;
        int crow = (r / cNW) * cNF + cN0 + (r % cNW);
        float* cRow = C + (size_t)crow * cPitch;
        #pragma unroll
        for (int ni = 0; ni < 4; ni++) {
            int col = colBase + tx * 4 + ni;
            if (col >= N) continue;
            float v = acc[mi][ni] + bias[col];
            if (addRes) cRow[col] += v; else cRow[col] = v;
        }
    }
}

// ------------------------- big SGEMM: 128x128 block, 8x8/thread, K=128 -----
__global__ void __launch_bounds__(256) sgemm128(
    const float* __restrict__ A, int aN0, int aNW, int aNF,
    const float* __restrict__ B, const float* __restrict__ bias,
    float* __restrict__ C, int cN0, int cNW, int cNF, int cPitch,
    int addRes)
{
    __shared__ float As[16][132];
    __shared__ float Bs[16][132];
    int tid = threadIdx.x;
    int tx = tid & 15, ty = tid >> 4;
    int rowBase = blockIdx.y * 128;
    int colBase = blockIdx.x * 128;

    float acc[8][8];
    #pragma unroll
    for (int i = 0; i < 8; i++)
        #pragma unroll
        for (int j = 0; j < 8; j++) acc[i][j] = 0.f;

    int lr = tid >> 1;
    int lk = (tid & 1) * 8;
    int ar = rowBase + lr;
    int arow = (ar / aNW) * aNF + aN0 + (ar % aNW);
    const float* aPtr = A + (size_t)arow * 128 + lk;
    const float* bPtr = B + (size_t)(colBase + lr) * 128 + lk;

    for (int kt = 0; kt < 8; kt++) {
        float4 a0 = *(const float4*)(aPtr + kt * 16);
        float4 a1 = *(const float4*)(aPtr + kt * 16 + 4);
        float4 b0 = *(const float4*)(bPtr + kt * 16);
        float4 b1 = *(const float4*)(bPtr + kt * 16 + 4);
        __syncthreads();
        As[lk + 0][lr] = a0.x; As[lk + 1][lr] = a0.y; As[lk + 2][lr] = a0.z; As[lk + 3][lr] = a0.w;
        As[lk + 4][lr] = a1.x; As[lk + 5][lr] = a1.y; As[lk + 6][lr] = a1.z; As[lk + 7][lr] = a1.w;
        Bs[lk + 0][lr] = b0.x; Bs[lk + 1][lr] = b0.y; Bs[lk + 2][lr] = b0.z; Bs[lk + 3][lr] = b0.w;
        Bs[lk + 4][lr] = b1.x; Bs[lk + 5][lr] = b1.y; Bs[lk + 6][lr] = b1.z; Bs[lk + 7][lr] = b1.w;
        __syncthreads();
        #pragma unroll
        for (int k = 0; k < 16; k++) {
            float4 A0 = *(const float4*)&As[k][ty * 8];
            float4 A1 = *(const float4*)&As[k][ty * 8 + 4];
            float4 B0 = *(const float4*)&Bs[k][tx * 8];
            float4 B1 = *(const float4*)&Bs[k][tx * 8 + 4];
            float ar8[8] = {A0.x, A0.y, A0.z, A0.w, A1.x, A1.y, A1.z, A1.w};
            float br8[8] = {B0.x, B0.y, B0.z, B0.w, B1.x, B1.y, B1.z, B1.w};
            #pragma unroll
            for (int i = 0; i < 8; i++)
                #pragma unroll
                for (int j = 0; j < 8; j++)
                    acc[i][j] = fmaf(ar8[i], br8[j], acc[i][j]);
        }
    }

    float4 bia0 = *(const float4*)(bias + colBase + tx * 8);
    float4 bia1 = *(const float4*)(bias + colBase + tx * 8 + 4);
    float bb[8] = {bia0.x, bia0.y, bia0.z, bia0.w, bia1.x, bia1.y, bia1.z, bia1.w};

    #pragma unroll
    for (int i = 0; i < 8; i++) {
        int r = rowBase + ty * 8 + i;
        int crow = (r / cNW) * cNF + cN0 + (r % cNW);
        float* cp = C + (size_t)crow * cPitch + colBase + tx * 8;
        float4 v0, v1;
        v0.x = acc[i][0] + bb[0]; v0.y = acc[i][1] + bb[1];
        v0.z = acc[i][2] + bb[2]; v0.w = acc[i][3] + bb[3];
        v1.x = acc[i][4] + bb[4]; v1.y = acc[i][5] + bb[5];
        v1.z = acc[i][6] + bb[6]; v1.w = acc[i][7] + bb[7];
        if (addRes) {
            float4 c0 = *(const float4*)cp;
            float4 c1 = *(const float4*)(cp + 4);
            v0.x += c0.x; v0.y += c0.y; v0.z += c0.z; v0.w += c0.w;
            v1.x += c1.x; v1.y += c1.y; v1.z += c1.z; v1.w += c1.w;
        }
        *(float4*)cp = v0;
        *(float4*)(cp + 4) = v1;
    }
}

// ------------------------- tf32 mma attention ------------------------------
// Block = (n, e, ih). Handles rows i in [ih*96, ih*96+96), all 192 cols.
// S[i][j] = Q[i]·K[j] + Q[i]·PK[d] + K[j]·PQ[d],  d = 191 - DSIGN*(i-j).
// Pass 1: Z1 = Q@PK over a d-window, scatter into S (j = f(i,d)).
// Pass 2: Z2 = K@PQ over a d-window, scatter-add into S (i = f(j,d)).
// Pass 3: S += Q@K^T.  Pass 4: exact row softmax.  Pass 5: O = P@V.
// smem floats: Q 96*33, K 192*33, V 192*33, Tb 32*289, S 96*193.
#define AT_SMEM ((96*33 + 192*33 + 192*33 + 32*289 + 96*193) * 4)

template<int DSIGN>
__global__ void __launch_bounds__(384, 1) attn_mma(
    const float* __restrict__ qPtr, int qPitch, int qOff,
    const float* __restrict__ kPtr, int kPitch, int kOff,
    const float* __restrict__ vPtr, int vPitch, int vOff,
    const float* __restrict__ proj, float* __restrict__ vo, int nB)
{
    extern __shared__ float sm[];
    float* Qs = sm;                    // [96][33]
    float* Ks = Qs + 96 * 33;          // [192][33]
    float* Vs = Ks + 192 * 33;         // [192][33]
    float* Tb = Vs + 192 * 33;         // [32][289]
    float* S  = Tb + 32 * 289;         // [96][193]

    int n = blockIdx.x, e = blockIdx.y;
    int i0 = blockIdx.z * 96;
    int tid = threadIdx.x;
    const float scale = 0.17677669529663687f;
    const int dbase = (DSIGN > 0) ? (96 - i0) : i0;

    for (int idx = tid; idx < 96 * 32; idx += 384) {
        int r = idx >> 5, c = idx & 31;
        Qs[r * 33 + c] = tf32r(qPtr[(size_t)((i0 + r) * nB + n) * qPitch + qOff + e * 32 + c] * scale);
    }
    for (int idx = tid; idx < 192 * 32; idx += 384) {
        int r = idx >> 5, c = idx & 31;
        size_t base = (size_t)(r * nB + n);
        Ks[r * 33 + c] = tf32r(kPtr[base * kPitch + kOff + e * 32 + c]);
        Vs[r * 33 + c] = tf32r(vPtr[base * vPitch + vOff + e * 32 + c]);
    }
    for (int idx = tid; idx < 32 * 289; idx += 384) {
        int c = idx / 289, dl = idx - c * 289;
        float v = 0.f;
        if (dl < 287) v = proj[(size_t)(dbase + dl) * 256 + 128 + e * 32 + c];   // pk
        Tb[c * 289 + dl] = tf32r(v);
    }
    __syncthreads();

    int warp = tid >> 5, lane = tid & 31, g = lane >> 2, tg = lane & 3;

    // ---- P1: z1 -> S (initializing writes) ----
    {
        int it = warp >> 1, h = warp & 1;
        int rbase = it * 16;
        unsigned a[4][4];
        #pragma unroll
        for (int ks = 0; ks < 4; ks++) {
            a[ks][0] = __float_as_uint(Qs[(rbase + g)     * 33 + ks * 8 + tg]);
            a[ks][1] = __float_as_uint(Qs[(rbase + g + 8) * 33 + ks * 8 + tg]);
            a[ks][2] = __float_as_uint(Qs[(rbase + g)     * 33 + ks * 8 + tg + 4]);
            a[ks][3] = __float_as_uint(Qs[(rbase + g + 8) * 33 + ks * 8 + tg + 4]);
        }
        int n0base = (DSIGN > 0) ? (80 - 16 * it) : (16 * it);
        for (int nt = h * 13; nt < h * 13 + 13; nt++) {
            int nd0 = n0base + nt * 8;
            float4 acc = make_float4(0.f, 0.f, 0.f, 0.f);
            #pragma unroll
            for (int ks = 0; ks < 4; ks++) {
                unsigned b0 = __float_as_uint(Tb[(ks * 8 + tg)     * 289 + nd0 + g]);
                unsigned b1 = __float_as_uint(Tb[(ks * 8 + tg + 4) * 289 + nd0 + g]);
                mma8(acc, a[ks], b0, b1);
            }
            int dl0 = nd0 + 2 * tg;
            int il0 = rbase + g, il1 = rbase + g + 8;
            // DSIGN>0: j = dl + iloc - 95 ; DSIGN<0: j = 191 + iloc - dl
            {
                int j;
                j = (DSIGN > 0) ? (dl0 + il0 - 95) : (191 + il0 - dl0);
                if (j >= 0 && j < 192) S[il0 * 193 + j] = acc.x;
                j = (DSIGN > 0) ? (dl0 + 1 + il0 - 95) : (191 + il0 - dl0 - 1);
                if (j >= 0 && j < 192) S[il0 * 193 + j] = acc.y;
                j = (DSIGN > 0) ? (dl0 + il1 - 95) : (191 + il1 - dl0);
                if (j >= 0 && j < 192) S[il1 * 193 + j] = acc.z;
                j = (DSIGN > 0) ? (dl0 + 1 + il1 - 95) : (191 + il1 - dl0 - 1);
                if (j >= 0 && j < 192) S[il1 * 193 + j] = acc.w;
            }
        }
    }
    __syncthreads();

    // ---- reload Tb with scaled PQ ----
    for (int idx = tid; idx < 32 * 289; idx += 384) {
        int c = idx / 289, dl = idx - c * 289;
        float v = 0.f;
        if (dl < 287) v = proj[(size_t)(dbase + dl) * 256 + e * 32 + c] * scale;  // pq (scaled)
        Tb[c * 289 + dl] = tf32r(v);
    }
    __syncthreads();

    // ---- P2: z2 scatter-add into S ----
    {
        int jG0 = warp * 16;
        unsigned a[4][4];
        #pragma unroll
        for (int ks = 0; ks < 4; ks++) {
            a[ks][0] = __float_as_uint(Ks[(jG0 + g)     * 33 + ks * 8 + tg]);
            a[ks][1] = __float_as_uint(Ks[(jG0 + g + 8) * 33 + ks * 8 + tg]);
            a[ks][2] = __float_as_uint(Ks[(jG0 + g)     * 33 + ks * 8 + tg + 4]);
            a[ks][3] = __float_as_uint(Ks[(jG0 + g + 8) * 33 + ks * 8 + tg + 4]);
        }
        int n0 = (DSIGN > 0) ? jG0 : (176 - jG0);
        for (int nt = 0; nt < 14; nt++) {
            int nd0 = n0 + nt * 8;
            float4 acc = make_float4(0.f, 0.f, 0.f, 0.f);
            #pragma unroll
            for (int ks = 0; ks < 4; ks++) {
                unsigned b0 = __float_as_uint(Tb[(ks * 8 + tg)     * 289 + nd0 + g]);
                unsigned b1 = __float_as_uint(Tb[(ks * 8 + tg + 4) * 289 + nd0 + g]);
                mma8(acc, a[ks], b0, b1);
            }
            int dl0 = nd0 + 2 * tg;
            int j0 = jG0 + g, j1 = jG0 + g + 8;
            // DSIGN>0: iloc = 95 + j - dl ; DSIGN<0: iloc = dl + j - 191
            {
                int il;
                il = (DSIGN > 0) ? (95 + j0 - dl0) : (dl0 + j0 - 191);
                if (il >= 0 && il < 96) S[il * 193 + j0] += acc.x;
                il = (DSIGN > 0) ? (95 + j0 - dl0 - 1) : (dl0 + 1 + j0 - 191);
                if (il >= 0 && il < 96) S[il * 193 + j0] += acc.y;
                il = (DSIGN > 0) ? (95 + j1 - dl0) : (dl0 + j1 - 191);
                if (il >= 0 && il < 96) S[il * 193 + j1] += acc.z;
                il = (DSIGN > 0) ? (95 + j1 - dl0 - 1) : (dl0 + 1 + j1 - 191);
                if (il >= 0 && il < 96) S[il * 193 + j1] += acc.w;
            }
        }
    }
    __syncthreads();

    // ---- P3: S += Q@K^T ----
    {
        int it = warp >> 1, h = warp & 1;
        int rbase = it * 16;
        unsigned a[4][4];
        #pragma unroll
        for (int ks = 0; ks < 4; ks++) {
            a[ks][0] = __float_as_uint(Qs[(rbase + g)     * 33 + ks * 8 + tg]);
            a[ks][1] = __float_as_uint(Qs[(rbase + g + 8) * 33 + ks * 8 + tg]);
            a[ks][2] = __float_as_uint(Qs[(rbase + g)     * 33 + ks * 8 + tg + 4]);
            a[ks][3] = __float_as_uint(Qs[(rbase + g + 8) * 33 + ks * 8 + tg + 4]);
        }
        for (int nt = h * 12; nt < h * 12 + 12; nt++) {
            int j0 = nt * 8;
            float4 acc = make_float4(0.f, 0.f, 0.f, 0.f);
            #pragma unroll
            for (int ks = 0; ks < 4; ks++) {
                unsigned b0 = __float_as_uint(Ks[(j0 + g) * 33 + ks * 8 + tg]);
                unsigned b1 = __float_as_uint(Ks[(j0 + g) * 33 + ks * 8 + tg + 4]);
                mma8(acc, a[ks], b0, b1);
            }
            int col = j0 + 2 * tg;
            S[(rbase + g)     * 193 + col]     += acc.x;
            S[(rbase + g)     * 193 + col + 1] += acc.y;
            S[(rbase + g + 8) * 193 + col]     += acc.z;
            S[(rbase + g + 8) * 193 + col + 1] += acc.w;
        }
    }
    __syncthreads();

    // ---- P4: exact row softmax, normalized P stored tf32-rounded ----
    {
        for (int r = warp * 8; r < warp * 8 + 8; r++) {
            float* row = &S[r * 193];
            float v[6];
            float mx = -1e30f;
            #pragma unroll
            for (int t = 0; t < 6; t++) { v[t] = row[lane + 32 * t]; mx = fmaxf(mx, v[t]); }
            #pragma unroll
            for (int o = 16; o > 0; o >>= 1) mx = fmaxf(mx, __shfl_xor_sync(0xffffffffu, mx, o));
            float sum = 0.f;
            #pragma unroll
            for (int t = 0; t < 6; t++) { v[t] = __expf(v[t] - mx); sum += v[t]; }
            #pragma unroll
            for (int o = 16; o > 0; o >>= 1) sum += __shfl_xor_sync(0xffffffffu, sum, o);
            float inv = 1.f / sum;
            #pragma unroll
            for (int t = 0; t < 6; t++) row[lane + 32 * t] = tf32r(v[t] * inv);
        }
    }
    __syncthreads();

    // ---- P5: O = P@V ----
    {
        int it = warp >> 1, h = warp & 1;
        int rbase = it * 16;
        int c0 = h * 16;
        float4 acc0 = make_float4(0.f, 0.f, 0.f, 0.f);
        float4 acc1 = make_float4(0.f, 0.f, 0.f, 0.f);
        for (int ks = 0; ks < 24; ks++) {
            unsigned a[4];
            a[0] = __float_as_uint(S[(rbase + g)     * 193 + ks * 8 + tg]);
            a[1] = __float_as_uint(S[(rbase + g + 8) * 193 + ks * 8 + tg]);
            a[2] = __float_as_uint(S[(rbase + g)     * 193 + ks * 8 + tg + 4]);
            a[3] = __float_as_uint(S[(rbase + g + 8) * 193 + ks * 8 + tg + 4]);
            unsigned b00 = __float_as_uint(Vs[(ks * 8 + tg)     * 33 + c0 + g]);
            unsigned b01 = __float_as_uint(Vs[(ks * 8 + tg + 4) * 33 + c0 + g]);
            unsigned b10 = __float_as_uint(Vs[(ks * 8 + tg)     * 33 + c0 + 8 + g]);
            unsigned b11 = __float_as_uint(Vs[(ks * 8 + tg + 4) * 33 + c0 + 8 + g]);
            mma8(acc0, a, b00, b01);
            mma8(acc1, a, b10, b11);
        }
        int i_a = i0 + rbase + g, i_b = i_a + 8;
        int colA = c0 + 2 * tg, colB = colA + 8;
        size_t oA = (size_t)(i_a * nB + n) * 128 + e * 32;
        size_t oB = (size_t)(i_b * nB + n) * 128 + e * 32;
        vo[oA + colA]     = acc0.x;
        vo[oA + colA + 1] = acc0.y;
        vo[oB + colA]     = acc0.z;
        vo[oB + colA + 1] = acc0.w;
        vo[oA + colB]     = acc1.x;
        vo[oA + colB + 1] = acc1.y;
        vo[oB + colB]     = acc1.z;
        vo[oB + colB + 1] = acc1.w;
    }
}

// ---------------------------------------------------------------------------
extern "C" void kernel_launch(void* const* d_in, const int* in_sizes, int n_in,
                              void* d_out, int out_size)
{
    (void)in_sizes; (void)n_in; (void)out_size;
    const float* feat_left  = (const float*)d_in[0];
    const float* feat_right = (const float*)d_in[1];
    const float* pos_enc    = (const float*)d_in[2];
    const float* s_iw = (const float*)d_in[3];
    const float* s_ib = (const float*)d_in[4];
    const float* s_ow = (const float*)d_in[5];
    const float* s_ob = (const float*)d_in[6];
    const float* s_g  = (const float*)d_in[7];
    const float* s_b  = (const float*)d_in[8];
    const float* c_iw = (const float*)d_in[9];
    const float* c_ib = (const float*)d_in[10];
    const float* c_ow = (const float*)d_in[11];
    const float* c_ob = (const float*)d_in[12];
    const float* c_g1 = (const float*)d_in[13];
    const float* c_b1 = (const float*)d_in[14];
    const float* c_g2 = (const float*)d_in[15];
    const float* c_b2 = (const float*)d_in[16];

    float* feat = (float*)d_out;

    float *ln_buf, *ln2_buf, *qkv, *vo, *projb;
    cudaGetSymbolAddress((void**)&ln_buf, g_ln);
    cudaGetSymbolAddress((void**)&ln2_buf, g_ln2);
    cudaGetSymbolAddress((void**)&qkv, g_qkv);
    cudaGetSymbolAddress((void**)&vo, g_vo);
    cudaGetSymbolAddress((void**)&projb, g_proj);
    float* projS = projb;
    float* projC = projb + 383 * 256;
    float* qb  = qkv;
    float* kvb = qkv + 192 * 128 * 128;

    cudaFuncSetAttribute(attn_mma<1>,  cudaFuncAttributeMaxDynamicSharedMemorySize, AT_SMEM);
    cudaFuncSetAttribute(attn_mma<-1>, cudaFuncAttributeMaxDynamicSharedMemorySize, AT_SMEM);

    build_feat<<<dim3(6, 4, 256), dim3(32, 32)>>>(feat_left, feat_right, feat);

    for (int L = 0; L < 4; L++) {
        const float* siw = s_iw + (size_t)L * 384 * 128;
        const float* sib = s_ib + (size_t)L * 384;
        const float* sow = s_ow + (size_t)L * 128 * 128;
        const float* sob = s_ob + (size_t)L * 128;
        const float* ciw = c_iw + (size_t)L * 384 * 128;
        const float* cib = c_ib + (size_t)L * 384;
        const float* cow = c_ow + (size_t)L * 128 * 128;
        const float* cob = c_ob + (size_t)L * 128;

        // ---------------- self-attention ----------------
        ln4_kernel<<<12288, 128>>>(feat, 0, 256, 256, s_g + L * 128, s_b + L * 128, ln_buf);
        sgemm64<<<dim3(4, 6), 256>>>(pos_enc, 0, 383, 383, siw, sib,
                                     projS, 0, 383, 383, 256, 383, 256, 0);
        sgemm128<<<dim3(3, 384), 256>>>(ln_buf, 0, 256, 256, siw, sib,
                                        qkv, 0, 256, 256, 384, 0);
        attn_mma<1><<<dim3(256, 4, 2), 384, AT_SMEM>>>(qkv, 384, 0, qkv, 384, 128,
                                                       qkv, 384, 256, projS, vo, 256);
        sgemm128<<<dim3(1, 384), 256>>>(vo, 0, 256, 256, sow, sob,
                                        feat, 0, 256, 256, 128, 1);

        // ---------------- cross-attention ----------------
        ln4_kernel<<<12288, 128>>>(feat, 0, 256, 256, c_g1 + L * 128, c_b1 + L * 128, ln_buf);
        sgemm64<<<dim3(4, 6), 256>>>(pos_enc, 0, 383, 383, ciw, cib,
                                     projC, 0, 383, 383, 256, 383, 256, 0);

        // fr update: q from fr2, kv from fl2, flipped table (DSIGN=-1)
        sgemm128<<<dim3(1, 192), 256>>>(ln_buf, 128, 128, 256, ciw, cib,
                                        qb, 0, 128, 128, 128, 0);
        sgemm128<<<dim3(2, 192), 256>>>(ln_buf, 0, 128, 256, ciw + 128 * 128, cib + 128,
                                        kvb, 0, 128, 128, 256, 0);
        attn_mma<-1><<<dim3(128, 4, 2), 384, AT_SMEM>>>(qb, 128, 0, kvb, 256, 0,
                                                        kvb, 256, 128, projC, vo, 128);
        sgemm128<<<dim3(1, 192), 256>>>(vo, 0, 128, 128, cow, cob,
                                        feat, 128, 128, 256, 128, 1);

        // fr2n = LN(updated fr)
        ln4_kernel<<<6144, 128>>>(feat, 128, 128, 256, c_g2 + L * 128, c_b2 + L * 128, ln2_buf);

        // fl update: q from fl2, kv from fr2n, normal table (DSIGN=+1)
        sgemm128<<<dim3(1, 192), 256>>>(ln_buf, 0, 128, 256, ciw, cib,
                                        qb, 0, 128, 128, 128, 0);
        sgemm128<<<dim3(2, 192), 256>>>(ln2_buf, 0, 128, 128, ciw + 128 * 128, cib + 128,
                                        kvb, 0, 128, 128, 256, 0);
        attn_mma<1><<<dim3(128, 4, 2), 384, AT_SMEM>>>(qb, 128, 0, kvb, 256, 0,
                                                       kvb, 256, 128, projC, vo, 128);
        sgemm128<<<dim3(1, 192), 256>>>(vo, 0, 128, 128, cow, cob,
                                        feat, 0, 128, 256, 128, 1);
    }
}

// round 4
// speedup vs baseline: 1.5035x; 1.5035x over previous
#include <cuda_runtime.h>
#include <cuda_bf16.h>
#include <math.h>

// ---------------------------------------------------------------------------
// STTM: 4-layer transformer, w=192, C=128, NHEAD=4, hd=32
// feat layout: (w, n, C) row-major. Self: n in [0,256). fl: n<128, fr: n>=128.
// Rel-pos: project pos_enc (383 rows) once per layer; attention gathers by
// d = 191 - DSIGN*(i-j). Projections on bf16 tensor cores (ldmatrix + mma),
// attention on the proven FFMA kernel (R2).
// ---------------------------------------------------------------------------

#define W_ 192
#define CC 128

// ------------------------- device scratch ---------------------------------
__device__ float g_ln [W_*256*CC];
__device__ float g_ln2[W_*128*CC];
__device__ float g_qkv[W_*256*3*CC];
__device__ float g_vo [W_*256*CC];
__device__ float g_proj[2*383*256];

// ------------------------- helpers -----------------------------------------
__device__ __forceinline__ unsigned pack_bf2(float x, float y) {
    __nv_bfloat162 h = __float22bfloat162_rn(make_float2(x, y));
    return *(unsigned*)&h;
}

__device__ __forceinline__ void ldm4(unsigned& r0, unsigned& r1, unsigned& r2, unsigned& r3,
                                     unsigned addr) {
    asm volatile("ldmatrix.sync.aligned.m8n8.x4.shared.b16 {%0,%1,%2,%3},[%4];"
                 : "=r"(r0), "=r"(r1), "=r"(r2), "=r"(r3) : "r"(addr));
}

__device__ __forceinline__ void mma_bf16(float* d, const unsigned* a, unsigned b0, unsigned b1) {
    asm volatile(
        "mma.sync.aligned.m16n8k16.row.col.f32.bf16.bf16.f32 "
        "{%0,%1,%2,%3},{%4,%5,%6,%7},{%8,%9},{%0,%1,%2,%3};"
        : "+f"(d[0]), "+f"(d[1]), "+f"(d[2]), "+f"(d[3])
        : "r"(a[0]), "r"(a[1]), "r"(a[2]), "r"(a[3]), "r"(b0), "r"(b1));
}

// ------------------------- build feat from inputs -------------------------
__global__ void build_feat(const float* __restrict__ L, const float* __restrict__ R,
                           float* __restrict__ feat)
{
    __shared__ float tile[32][33];
    int n = blockIdx.z;
    const float* src = (n < 128) ? L : R;
    int nn = n & 127;
    int h = nn >> 1, b = nn & 1;
    int i = blockIdx.x * 32 + threadIdx.x;
    int c = blockIdx.y * 32 + threadIdx.y;
    tile[threadIdx.y][threadIdx.x] = src[(((size_t)b * 128 + c) * 64 + h) * 192 + i];
    __syncthreads();
    int i2 = blockIdx.x * 32 + threadIdx.y;
    int c2 = blockIdx.y * 32 + threadIdx.x;
    feat[((size_t)i2 * 256 + n) * 128 + c2] = tile[threadIdx.x][threadIdx.y];
}

// ------------------------- LayerNorm: 1 warp per row, 4 rows/block ---------
__global__ void ln4_kernel(const float* __restrict__ x, int n0, int nW, int nF,
                           const float* __restrict__ g, const float* __restrict__ b,
                           float* __restrict__ y)
{
    int t = blockIdx.x * 4 + (threadIdx.x >> 5);
    int lane = threadIdx.x & 31;
    int row = (t / nW) * nF + n0 + (t % nW);
    float4 v = *(const float4*)(x + (size_t)row * 128 + lane * 4);
    float s  = v.x + v.y + v.z + v.w;
    float sq = v.x*v.x + v.y*v.y + v.z*v.z + v.w*v.w;
    #pragma unroll
    for (int o = 16; o > 0; o >>= 1) {
        s  += __shfl_xor_sync(0xffffffffu, s,  o);
        sq += __shfl_xor_sync(0xffffffffu, sq, o);
    }
    float mean = s * (1.f / 128.f);
    float var  = sq * (1.f / 128.f) - mean * mean;
    float inv = rsqrtf(var + 1e-5f);
    float4 gv = *(const float4*)(g + lane * 4);
    float4 bv = *(const float4*)(b + lane * 4);
    float4 o4;
    o4.x = (v.x - mean) * inv * gv.x + bv.x;
    o4.y = (v.y - mean) * inv * gv.y + bv.y;
    o4.z = (v.z - mean) * inv * gv.z + bv.z;
    o4.w = (v.w - mean) * inv * gv.w + bv.w;
    *(float4*)(y + (size_t)t * 128 + lane * 4) = o4;
}

// ------------------------- small SGEMM (64x64 tiles, bounds-checked) -------
__global__ void sgemm64(const float* __restrict__ A, int aN0, int aNW, int aNF,
                        const float* __restrict__ B, const float* __restrict__ bias,
                        float* __restrict__ C, int cN0, int cNW, int cNF, int cPitch,
                        int M, int N, int addRes)
{
    __shared__ float As[16][68];
    __shared__ float Bs[16][68];
    int tid = threadIdx.x;
    int tx = tid & 15, ty = tid >> 4;
    int rowBase = blockIdx.y * 64;
    int colBase = blockIdx.x * 64;

    float acc[4][4];
    #pragma unroll
    for (int i = 0; i < 4; i++)
        #pragma unroll
        for (int j = 0; j < 4; j++) acc[i][j] = 0.f;

    int lr = tid >> 2;
    int lc = (tid & 3) * 4;
    int ar = rowBase + lr;
    const float* aRowPtr = nullptr;
    if (ar < M) {
        int arow = (ar / aNW) * aNF + aN0 + (ar % aNW);
        aRowPtr = A + (size_t)arow * 128;
    }
    int bc = colBase + lr;
    const float* bRowPtr = (bc < N) ? (B + (size_t)bc * 128) : nullptr;

    for (int kt = 0; kt < 8; kt++) {
        int k0 = kt * 16 + lc;
        float4 av = aRowPtr ? *(const float4*)(aRowPtr + k0) : make_float4(0, 0, 0, 0);
        float4 bv = bRowPtr ? *(const float4*)(bRowPtr + k0) : make_float4(0, 0, 0, 0);
        As[lc + 0][lr] = av.x; As[lc + 1][lr] = av.y; As[lc + 2][lr] = av.z; As[lc + 3][lr] = av.w;
        Bs[lc + 0][lr] = bv.x; Bs[lc + 1][lr] = bv.y; Bs[lc + 2][lr] = bv.z; Bs[lc + 3][lr] = bv.w;
        __syncthreads();
        #pragma unroll
        for (int k = 0; k < 16; k++) {
            float a0 = As[k][ty * 4 + 0], a1 = As[k][ty * 4 + 1];
            float a2 = As[k][ty * 4 + 2], a3 = As[k][ty * 4 + 3];
            float b0 = Bs[k][tx * 4 + 0], b1 = Bs[k][tx * 4 + 1];
            float b2 = Bs[k][tx * 4 + 2], b3 = Bs[k][tx * 4 + 3];
            acc[0][0] = fmaf(a0, b0, acc[0][0]); acc[0][1] = fmaf(a0, b1, acc[0][1]);
            acc[0][2] = fmaf(a0, b2, acc[0][2]); acc[0][3] = fmaf(a0, b3, acc[0][3]);
            acc[1][0] = fmaf(a1, b0, acc[1][0]); acc[1][1] = fmaf(a1, b1, acc[1][1]);
            acc[1][2] = fmaf(a1, b2, acc[1][2]); acc[1][3] = fmaf(a1, b3, acc[1][3]);
            acc[2][0] = fmaf(a2, b0, acc[2][0]); acc[2][1] = fmaf(a2, b1, acc[2][1]);
            acc[2][2] = fmaf(a2, b2, acc[2][2]); acc[2][3] = fmaf(a2, b3, acc[2][3]);
            acc[3][0] = fmaf(a3, b0, acc[3][0]); acc[3][1] = fmaf(a3, b1, acc[3][1]);
            acc[3][2] = fmaf(a3, b2, acc[3][2]); acc[3][3] = fmaf(a3, b3, acc[3][3]);
        }
        __syncthreads();
    }

    #pragma unroll
    for (int mi = 0; mi < 4; mi++) {
        int r = rowBase + ty * 4 + mi;
        if (r >= M) continue;
        int crow = (r / cNW) * cNF + cN0 + (r % cNW);
        float* cRow = C + (size_t)crow * cPitch;
        #pragma unroll
        for (int ni = 0; ni < 4; ni++) {
            int col = colBase + tx * 4 + ni;
            if (col >= N) continue;
            float v = acc[mi][ni] + bias[col];
            if (addRes) cRow[col] += v; else cRow[col] = v;
        }
    }
}

// ------------------------- bf16 tensor-core GEMM ---------------------------
// C[r, col] = sum_k A[map(r),k] * B[col,k] + bias[col], K=128 fixed.
// Block 128x128, 256 threads = 8 warps (4 m x 2 n), warp tile 32m x 64n.
// A,B converted fp32->bf16 inline into XOR-swizzled smem; ldmatrix fragments.
// Requires M%128==0, N%128==0 (all call sites satisfy this).
#define HSMEM (2 * 128 * 128 * 2)

__global__ void __launch_bounds__(256) hgemm(
    const float* __restrict__ A, int aN0, int aNW, int aNF,
    const float* __restrict__ B, const float* __restrict__ bias,
    float* __restrict__ C, int cN0, int cNW, int cNF, int cPitch,
    int addRes)
{
    extern __shared__ __nv_bfloat16 hsm[];
    __nv_bfloat16* As = hsm;            // [128][128] swizzled
    __nv_bfloat16* Bs = hsm + 128*128;  // [128][128] swizzled

    int tid = threadIdx.x;
    int rowBase = blockIdx.y * 128;
    int colBase = blockIdx.x * 128;

    // ---- load + convert: 2 threads per row, 64 k each ----
    int lr = tid >> 1, lkh = tid & 1;
    {
        int ar = rowBase + lr;
        int arow = (ar / aNW) * aNF + aN0 + (ar % aNW);
        const float* ap = A + (size_t)arow * 128 + lkh * 64;
        const float* bp = B + (size_t)(colBase + lr) * 128 + lkh * 64;
        int sw = lr & 7;
        #pragma unroll
        for (int j = 0; j < 8; j++) {
            int c = lkh * 8 + j;
            int cp = c ^ sw;
            float4 v0 = *(const float4*)(ap + j * 8);
            float4 v1 = *(const float4*)(ap + j * 8 + 4);
            uint4 u;
            u.x = pack_bf2(v0.x, v0.y); u.y = pack_bf2(v0.z, v0.w);
            u.z = pack_bf2(v1.x, v1.y); u.w = pack_bf2(v1.z, v1.w);
            *(uint4*)&As[lr * 128 + cp * 8] = u;
            v0 = *(const float4*)(bp + j * 8);
            v1 = *(const float4*)(bp + j * 8 + 4);
            u.x = pack_bf2(v0.x, v0.y); u.y = pack_bf2(v0.z, v0.w);
            u.z = pack_bf2(v1.x, v1.y); u.w = pack_bf2(v1.z, v1.w);
            *(uint4*)&Bs[lr * 128 + cp * 8] = u;
        }
    }
    __syncthreads();

    int wid = tid >> 5, lane = tid & 31;
    int wm = (wid & 3) * 32;      // warp m offset
    int wn = (wid >> 2) * 64;     // warp n offset
    int g = lane >> 2, tg = lane & 3;

    float acc[2][8][4];
    #pragma unroll
    for (int mt = 0; mt < 2; mt++)
        #pragma unroll
        for (int nt = 0; nt < 8; nt++)
            #pragma unroll
            for (int q = 0; q < 4; q++) acc[mt][nt][q] = 0.f;

    unsigned asBase = (unsigned)__cvta_generic_to_shared(As);
    unsigned bsBase = (unsigned)__cvta_generic_to_shared(Bs);

    #pragma unroll
    for (int ks = 0; ks < 8; ks++) {
        int c0 = ks * 2;   // 16B-chunk index of k0
        // A fragments: 2 m16 tiles
        unsigned afr[2][4];
        #pragma unroll
        for (int mt = 0; mt < 2; mt++) {
            int row = wm + mt * 16 + (lane & 15);
            int ch = c0 + (lane >> 4);
            unsigned addr = asBase + (unsigned)((row * 128 + ((ch ^ (row & 7)) << 3)) * 2);
            ldm4(afr[mt][0], afr[mt][1], afr[mt][2], afr[mt][3], addr);
        }
        // B fragments: 8 n8 tiles via 4 ldmatrix.x4
        unsigned bfr[8][2];
        #pragma unroll
        for (int p = 0; p < 4; p++) {
            int row = wn + p * 16 + (lane & 7) + ((lane >> 4) << 3);
            int ch = c0 + ((lane >> 3) & 1);
            unsigned addr = bsBase + (unsigned)((row * 128 + ((ch ^ (row & 7)) << 3)) * 2);
            unsigned r0, r1, r2, r3;
            ldm4(r0, r1, r2, r3, addr);
            bfr[p * 2][0] = r0;     bfr[p * 2][1] = r1;
            bfr[p * 2 + 1][0] = r2; bfr[p * 2 + 1][1] = r3;
        }
        #pragma unroll
        for (int mt = 0; mt < 2; mt++)
            #pragma unroll
            for (int nt = 0; nt < 8; nt++)
                mma_bf16(acc[mt][nt], afr[mt], bfr[nt][0], bfr[nt][1]);
    }

    // ---- epilogue ----
    #pragma unroll
    for (int mt = 0; mt < 2; mt++) {
        int r0g = rowBase + wm + mt * 16 + g;
        #pragma unroll
        for (int half = 0; half < 2; half++) {
            int r = r0g + half * 8;
            int crow = (r / cNW) * cNF + cN0 + (r % cNW);
            float* cRow = C + (size_t)crow * cPitch;
            #pragma unroll
            for (int nt = 0; nt < 8; nt++) {
                int col = colBase + wn + nt * 8 + 2 * tg;
                float2 b2 = *(const float2*)(bias + col);
                float vx = acc[mt][nt][half * 2 + 0] + b2.x;
                float vy = acc[mt][nt][half * 2 + 1] + b2.y;
                if (addRes) {
                    float2 old = *(const float2*)(cRow + col);
                    vx += old.x; vy += old.y;
                }
                float2 o2; o2.x = vx; o2.y = vy;
                *(float2*)(cRow + col) = o2;
            }
        }
    }
}

// ------------------------- fused rel-pos attention (FFMA, 4x4 tiles) -------
#define ATTN_SMEM ((32*196*2 + 192*36 + 32*384*2) * 4)

template<int DSIGN>
__global__ void __launch_bounds__(384, 1) attn_kernel(
    const float* __restrict__ qPtr, int qPitch, int qOff,
    const float* __restrict__ kPtr, int kPitch, int kOff,
    const float* __restrict__ vPtr, int vPitch, int vOff,
    const float* __restrict__ proj, float* __restrict__ vo, int nB)
{
    extern __shared__ float sm[];
    float* qT  = sm;               // [32][196]
    float* kT  = qT  + 32 * 196;   // [32][196]
    float* v_s = kT  + 32 * 196;   // [192][36]
    float* pqT = v_s + 192 * 36;   // [32][384]
    float* pkT = pqT + 32 * 384;   // [32][384]

    int n = blockIdx.x, e = blockIdx.y, tid = threadIdx.x;
    const float scale = 0.17677669529663687f;

    for (int idx = tid; idx < 192 * 32; idx += 384) {
        int i = idx >> 5, c = idx & 31;
        size_t base = (size_t)(i * nB + n);
        qT[c * 196 + i] = qPtr[base * qPitch + qOff + e * 32 + c] * scale;
        kT[c * 196 + i] = kPtr[base * kPitch + kOff + e * 32 + c];
        v_s[i * 36 + c] = vPtr[base * vPitch + vOff + e * 32 + c];
    }
    for (int idx = tid; idx < 383 * 32; idx += 384) {
        int d = idx >> 5, c = idx & 31;
        pqT[c * 384 + d] = proj[(size_t)d * 256 + e * 32 + c] * scale;
        pkT[c * 384 + d] = proj[(size_t)d * 256 + 128 + e * 32 + c];
    }
    __syncthreads();

    int warp = tid >> 5, lane = tid & 31;
    int rg = lane >> 3, jg = lane & 7;
    int i0 = warp * 16 + rg * 4;

    float o[4][4];
    float m[4], l[4];
    #pragma unroll
    for (int di = 0; di < 4; di++) {
        m[di] = -1e30f; l[di] = 0.f;
        #pragma unroll
        for (int vc = 0; vc < 4; vc++) o[di][vc] = 0.f;
    }

    #pragma unroll 1
    for (int jt = 0; jt < 6; jt++) {
        int j0 = jt * 32 + jg * 4;
        int pb = (DSIGN > 0) ? (188 - i0 + j0) : (188 + i0 - j0);

        float s[4][4];
        #pragma unroll
        for (int di = 0; di < 4; di++)
            #pragma unroll
            for (int dj = 0; dj < 4; dj++) s[di][dj] = 0.f;

        #pragma unroll
        for (int c = 0; c < 32; c++) {
            float4 qv = *(const float4*)&qT[c * 196 + i0];
            float4 kv = *(const float4*)&kT[c * 196 + j0];
            const float* pkb = &pkT[c * 384 + pb];
            const float* pqb = &pqT[c * 384 + pb];
            float4 pkA = *(const float4*)pkb;
            float4 pkB = *(const float4*)(pkb + 4);
            float4 pqA = *(const float4*)pqb;
            float4 pqB = *(const float4*)(pqb + 4);
            float qa[4] = {qv.x, qv.y, qv.z, qv.w};
            float ka[4] = {kv.x, kv.y, kv.z, kv.w};
            float pk8[8] = {pkA.x, pkA.y, pkA.z, pkA.w, pkB.x, pkB.y, pkB.z, pkB.w};
            float pq8[8] = {pqA.x, pqA.y, pqA.z, pqA.w, pqB.x, pqB.y, pqB.z, pqB.w};
            #pragma unroll
            for (int di = 0; di < 4; di++) {
                #pragma unroll
                for (int dj = 0; dj < 4; dj++) {
                    const int ix = (DSIGN > 0) ? (3 - di + dj) : (3 + di - dj);
                    float acc = s[di][dj];
                    acc = fmaf(qa[di], ka[dj], acc);
                    acc = fmaf(qa[di], pk8[ix], acc);
                    acc = fmaf(ka[dj], pq8[ix], acc);
                    s[di][dj] = acc;
                }
            }
        }

        #pragma unroll
        for (int di = 0; di < 4; di++) {
            float mx = fmaxf(fmaxf(s[di][0], s[di][1]), fmaxf(s[di][2], s[di][3]));
            mx = fmaxf(mx, __shfl_xor_sync(0xffffffffu, mx, 1));
            mx = fmaxf(mx, __shfl_xor_sync(0xffffffffu, mx, 2));
            mx = fmaxf(mx, __shfl_xor_sync(0xffffffffu, mx, 4));
            float mn = fmaxf(m[di], mx);
            float corr = __expf(m[di] - mn);
            float rs = 0.f;
            #pragma unroll
            for (int dj = 0; dj < 4; dj++) {
                s[di][dj] = __expf(s[di][dj] - mn);
                rs += s[di][dj];
            }
            rs += __shfl_xor_sync(0xffffffffu, rs, 1);
            rs += __shfl_xor_sync(0xffffffffu, rs, 2);
            rs += __shfl_xor_sync(0xffffffffu, rs, 4);
            l[di] = l[di] * corr + rs;
            #pragma unroll
            for (int vc = 0; vc < 4; vc++) o[di][vc] *= corr;
            m[di] = mn;
        }

        int jbase = jt * 32;
        #pragma unroll
        for (int j = 0; j < 32; j++) {
            int src = rg * 8 + (j >> 2);
            float4 vv = *(const float4*)&v_s[(jbase + j) * 36 + jg * 4];
            #pragma unroll
            for (int di = 0; di < 4; di++) {
                float pj = __shfl_sync(0xffffffffu, s[di][j & 3], src);
                o[di][0] = fmaf(pj, vv.x, o[di][0]);
                o[di][1] = fmaf(pj, vv.y, o[di][1]);
                o[di][2] = fmaf(pj, vv.z, o[di][2]);
                o[di][3] = fmaf(pj, vv.w, o[di][3]);
            }
        }
    }

    #pragma unroll
    for (int di = 0; di < 4; di++) {
        float inv = 1.0f / l[di];
        int ri = i0 + di;
        float4 ov;
        ov.x = o[di][0] * inv; ov.y = o[di][1] * inv;
        ov.z = o[di][2] * inv; ov.w = o[di][3] * inv;
        *(float4*)&vo[((size_t)(ri * nB + n)) * 128 + e * 32 + jg * 4] = ov;
    }
}

// ---------------------------------------------------------------------------
extern "C" void kernel_launch(void* const* d_in, const int* in_sizes, int n_in,
                              void* d_out, int out_size)
{
    (void)in_sizes; (void)n_in; (void)out_size;
    const float* feat_left  = (const float*)d_in[0];
    const float* feat_right = (const float*)d_in[1];
    const float* pos_enc    = (const float*)d_in[2];
    const float* s_iw = (const float*)d_in[3];
    const float* s_ib = (const float*)d_in[4];
    const float* s_ow = (const float*)d_in[5];
    const float* s_ob = (const float*)d_in[6];
    const float* s_g  = (const float*)d_in[7];
    const float* s_b  = (const float*)d_in[8];
    const float* c_iw = (const float*)d_in[9];
    const float* c_ib = (const float*)d_in[10];
    const float* c_ow = (const float*)d_in[11];
    const float* c_ob = (const float*)d_in[12];
    const float* c_g1 = (const float*)d_in[13];
    const float* c_b1 = (const float*)d_in[14];
    const float* c_g2 = (const float*)d_in[15];
    const float* c_b2 = (const float*)d_in[16];

    float* feat = (float*)d_out;

    float *ln_buf, *ln2_buf, *qkv, *vo, *projb;
    cudaGetSymbolAddress((void**)&ln_buf, g_ln);
    cudaGetSymbolAddress((void**)&ln2_buf, g_ln2);
    cudaGetSymbolAddress((void**)&qkv, g_qkv);
    cudaGetSymbolAddress((void**)&vo, g_vo);
    cudaGetSymbolAddress((void**)&projb, g_proj);
    float* projS = projb;
    float* projC = projb + 383 * 256;
    float* qb  = qkv;
    float* kvb = qkv + 192 * 128 * 128;

    cudaFuncSetAttribute(attn_kernel<1>,  cudaFuncAttributeMaxDynamicSharedMemorySize, ATTN_SMEM);
    cudaFuncSetAttribute(attn_kernel<-1>, cudaFuncAttributeMaxDynamicSharedMemorySize, ATTN_SMEM);
    cudaFuncSetAttribute(hgemm, cudaFuncAttributeMaxDynamicSharedMemorySize, HSMEM);

    build_feat<<<dim3(6, 4, 256), dim3(32, 32)>>>(feat_left, feat_right, feat);

    for (int L = 0; L < 4; L++) {
        const float* siw = s_iw + (size_t)L * 384 * 128;
        const float* sib = s_ib + (size_t)L * 384;
        const float* sow = s_ow + (size_t)L * 128 * 128;
        const float* sob = s_ob + (size_t)L * 128;
        const float* ciw = c_iw + (size_t)L * 384 * 128;
        const float* cib = c_ib + (size_t)L * 384;
        const float* cow = c_ow + (size_t)L * 128 * 128;
        const float* cob = c_ob + (size_t)L * 128;

        // ---------------- self-attention ----------------
        ln4_kernel<<<12288, 128>>>(feat, 0, 256, 256, s_g + L * 128, s_b + L * 128, ln_buf);
        sgemm64<<<dim3(4, 6), 256>>>(pos_enc, 0, 383, 383, siw, sib,
                                     projS, 0, 383, 383, 256, 383, 256, 0);
        hgemm<<<dim3(3, 384), 256, HSMEM>>>(ln_buf, 0, 256, 256, siw, sib,
                                            qkv, 0, 256, 256, 384, 0);
        attn_kernel<1><<<dim3(256, 4), 384, ATTN_SMEM>>>(qkv, 384, 0, qkv, 384, 128,
                                                         qkv, 384, 256, projS, vo, 256);
        hgemm<<<dim3(1, 384), 256, HSMEM>>>(vo, 0, 256, 256, sow, sob,
                                            feat, 0, 256, 256, 128, 1);

        // ---------------- cross-attention ----------------
        ln4_kernel<<<12288, 128>>>(feat, 0, 256, 256, c_g1 + L * 128, c_b1 + L * 128, ln_buf);
        sgemm64<<<dim3(4, 6), 256>>>(pos_enc, 0, 383, 383, ciw, cib,
                                     projC, 0, 383, 383, 256, 383, 256, 0);

        // fr update: q from fr2, kv from fl2, flipped table (DSIGN=-1)
        hgemm<<<dim3(1, 192), 256, HSMEM>>>(ln_buf, 128, 128, 256, ciw, cib,
                                            qb, 0, 128, 128, 128, 0);
        hgemm<<<dim3(2, 192), 256, HSMEM>>>(ln_buf, 0, 128, 256, ciw + 128 * 128, cib + 128,
                                            kvb, 0, 128, 128, 256, 0);
        attn_kernel<-1><<<dim3(128, 4), 384, ATTN_SMEM>>>(qb, 128, 0, kvb, 256, 0,
                                                          kvb, 256, 128, projC, vo, 128);
        hgemm<<<dim3(1, 192), 256, HSMEM>>>(vo, 0, 128, 128, cow, cob,
                                            feat, 128, 128, 256, 128, 1);

        // fr2n = LN(updated fr)
        ln4_kernel<<<6144, 128>>>(feat, 128, 128, 256, c_g2 + L * 128, c_b2 + L * 128, ln2_buf);

        // fl update: q from fl2, kv from fr2n, normal table (DSIGN=+1)
        hgemm<<<dim3(1, 192), 256, HSMEM>>>(ln_buf, 0, 128, 256, ciw, cib,
                                            qb, 0, 128, 128, 128, 0);
        hgemm<<<dim3(2, 192), 256, HSMEM>>>(ln2_buf, 0, 128, 128, ciw + 128 * 128, cib + 128,
                                            kvb, 0, 128, 128, 256, 0);
        attn_kernel<1><<<dim3(128, 4), 384, ATTN_SMEM>>>(qb, 128, 0, kvb, 256, 0,
                                                         kvb, 256, 128, projC, vo, 128);
        hgemm<<<dim3(1, 192), 256, HSMEM>>>(vo, 0, 128, 128, cow, cob,
                                            feat, 0, 128, 256, 128, 1);
    }
}

// round 5
// speedup vs baseline: 2.3921x; 1.5910x over previous
#include <cuda_runtime.h>
#include <cuda_bf16.h>
#include <math.h>

// ---------------------------------------------------------------------------
// STTM: 4-layer transformer, w=192, C=128, NHEAD=4, hd=32
// feat layout: (w, n, C) row-major. Self: n in [0,256). fl: n<128, fr: n>=128.
// Rel-pos: project pos_enc (383 rows) once per layer.
// Attention: bf16 mma for all four GEMM-shaped pieces (Z1=Q@PK^T, Z2=K@PQ^T,
// QK^T, P@V), with skew-stored Z1/Z2 so score assembly is direct-addressed.
// Projections: bf16 mma hgemm (R4).
// ---------------------------------------------------------------------------

#define W_ 192
#define CC 128

// ------------------------- device scratch ---------------------------------
__device__ float g_ln [W_*256*CC];
__device__ float g_ln2[W_*128*CC];
__device__ float g_qkv[W_*256*3*CC];
__device__ float g_vo [W_*256*CC];
__device__ float g_proj[2*383*256];

// ------------------------- helpers -----------------------------------------
__device__ __forceinline__ unsigned pack_bf2(float x, float y) {
    __nv_bfloat162 h = __float22bfloat162_rn(make_float2(x, y));
    return *(unsigned*)&h;
}
__device__ __forceinline__ uint2 pack4(float4 v) {
    uint2 u; u.x = pack_bf2(v.x, v.y); u.y = pack_bf2(v.z, v.w); return u;
}
__device__ __forceinline__ uint2 pack4s(float4 v, float s) {
    uint2 u; u.x = pack_bf2(v.x * s, v.y * s); u.y = pack_bf2(v.z * s, v.w * s); return u;
}

__device__ __forceinline__ void ldm4(unsigned& r0, unsigned& r1, unsigned& r2, unsigned& r3,
                                     unsigned addr) {
    asm volatile("ldmatrix.sync.aligned.m8n8.x4.shared.b16 {%0,%1,%2,%3},[%4];"
                 : "=r"(r0), "=r"(r1), "=r"(r2), "=r"(r3) : "r"(addr));
}

__device__ __forceinline__ void mma_bf16(float* d, const unsigned* a, unsigned b0, unsigned b1) {
    asm volatile(
        "mma.sync.aligned.m16n8k16.row.col.f32.bf16.bf16.f32 "
        "{%0,%1,%2,%3},{%4,%5,%6,%7},{%8,%9},{%0,%1,%2,%3};"
        : "+f"(d[0]), "+f"(d[1]), "+f"(d[2]), "+f"(d[3])
        : "r"(a[0]), "r"(a[1]), "r"(a[2]), "r"(a[3]), "r"(b0), "r"(b1));
}

// ------------------------- build feat from inputs -------------------------
__global__ void build_feat(const float* __restrict__ L, const float* __restrict__ R,
                           float* __restrict__ feat)
{
    __shared__ float tile[32][33];
    int n = blockIdx.z;
    const float* src = (n < 128) ? L : R;
    int nn = n & 127;
    int h = nn >> 1, b = nn & 1;
    int i = blockIdx.x * 32 + threadIdx.x;
    int c = blockIdx.y * 32 + threadIdx.y;
    tile[threadIdx.y][threadIdx.x] = src[(((size_t)b * 128 + c) * 64 + h) * 192 + i];
    __syncthreads();
    int i2 = blockIdx.x * 32 + threadIdx.y;
    int c2 = blockIdx.y * 32 + threadIdx.x;
    feat[((size_t)i2 * 256 + n) * 128 + c2] = tile[threadIdx.x][threadIdx.y];
}

// ------------------------- LayerNorm: 1 warp per row, 4 rows/block ---------
__global__ void ln4_kernel(const float* __restrict__ x, int n0, int nW, int nF,
                           const float* __restrict__ g, const float* __restrict__ b,
                           float* __restrict__ y)
{
    int t = blockIdx.x * 4 + (threadIdx.x >> 5);
    int lane = threadIdx.x & 31;
    int row = (t / nW) * nF + n0 + (t % nW);
    float4 v = *(const float4*)(x + (size_t)row * 128 + lane * 4);
    float s  = v.x + v.y + v.z + v.w;
    float sq = v.x*v.x + v.y*v.y + v.z*v.z + v.w*v.w;
    #pragma unroll
    for (int o = 16; o > 0; o >>= 1) {
        s  += __shfl_xor_sync(0xffffffffu, s,  o);
        sq += __shfl_xor_sync(0xffffffffu, sq, o);
    }
    float mean = s * (1.f / 128.f);
    float var  = sq * (1.f / 128.f) - mean * mean;
    float inv = rsqrtf(var + 1e-5f);
    float4 gv = *(const float4*)(g + lane * 4);
    float4 bv = *(const float4*)(b + lane * 4);
    float4 o4;
    o4.x = (v.x - mean) * inv * gv.x + bv.x;
    o4.y = (v.y - mean) * inv * gv.y + bv.y;
    o4.z = (v.z - mean) * inv * gv.z + bv.z;
    o4.w = (v.w - mean) * inv * gv.w + bv.w;
    *(float4*)(y + (size_t)t * 128 + lane * 4) = o4;
}

// ------------------------- small SGEMM (64x64 tiles, bounds-checked) -------
__global__ void sgemm64(const float* __restrict__ A, int aN0, int aNW, int aNF,
                        const float* __restrict__ B, const float* __restrict__ bias,
                        float* __restrict__ C, int cN0, int cNW, int cNF, int cPitch,
                        int M, int N, int addRes)
{
    __shared__ float As[16][68];
    __shared__ float Bs[16][68];
    int tid = threadIdx.x;
    int tx = tid & 15, ty = tid >> 4;
    int rowBase = blockIdx.y * 64;
    int colBase = blockIdx.x * 64;

    float acc[4][4];
    #pragma unroll
    for (int i = 0; i < 4; i++)
        #pragma unroll
        for (int j = 0; j < 4; j++) acc[i][j] = 0.f;

    int lr = tid >> 2;
    int lc = (tid & 3) * 4;
    int ar = rowBase + lr;
    const float* aRowPtr = nullptr;
    if (ar < M) {
        int arow = (ar / aNW) * aNF + aN0 + (ar % aNW);
        aRowPtr = A + (size_t)arow * 128;
    }
    int bc = colBase + lr;
    const float* bRowPtr = (bc < N) ? (B + (size_t)bc * 128) : nullptr;

    for (int kt = 0; kt < 8; kt++) {
        int k0 = kt * 16 + lc;
        float4 av = aRowPtr ? *(const float4*)(aRowPtr + k0) : make_float4(0, 0, 0, 0);
        float4 bv = bRowPtr ? *(const float4*)(bRowPtr + k0) : make_float4(0, 0, 0, 0);
        As[lc + 0][lr] = av.x; As[lc + 1][lr] = av.y; As[lc + 2][lr] = av.z; As[lc + 3][lr] = av.w;
        Bs[lc + 0][lr] = bv.x; Bs[lc + 1][lr] = bv.y; Bs[lc + 2][lr] = bv.z; Bs[lc + 3][lr] = bv.w;
        __syncthreads();
        #pragma unroll
        for (int k = 0; k < 16; k++) {
            float a0 = As[k][ty * 4 + 0], a1 = As[k][ty * 4 + 1];
            float a2 = As[k][ty * 4 + 2], a3 = As[k][ty * 4 + 3];
            float b0 = Bs[k][tx * 4 + 0], b1 = Bs[k][tx * 4 + 1];
            float b2 = Bs[k][tx * 4 + 2], b3 = Bs[k][tx * 4 + 3];
            acc[0][0] = fmaf(a0, b0, acc[0][0]); acc[0][1] = fmaf(a0, b1, acc[0][1]);
            acc[0][2] = fmaf(a0, b2, acc[0][2]); acc[0][3] = fmaf(a0, b3, acc[0][3]);
            acc[1][0] = fmaf(a1, b0, acc[1][0]); acc[1][1] = fmaf(a1, b1, acc[1][1]);
            acc[1][2] = fmaf(a1, b2, acc[1][2]); acc[1][3] = fmaf(a1, b3, acc[1][3]);
            acc[2][0] = fmaf(a2, b0, acc[2][0]); acc[2][1] = fmaf(a2, b1, acc[2][1]);
            acc[2][2] = fmaf(a2, b2, acc[2][2]); acc[2][3] = fmaf(a2, b3, acc[2][3]);
            acc[3][0] = fmaf(a3, b0, acc[3][0]); acc[3][1] = fmaf(a3, b1, acc[3][1]);
            acc[3][2] = fmaf(a3, b2, acc[3][2]); acc[3][3] = fmaf(a3, b3, acc[3][3]);
        }
        __syncthreads();
    }

    #pragma unroll
    for (int mi = 0; mi < 4; mi++) {
        int r = rowBase + ty * 4 + mi;
        if (r >= M) continue;
        int crow = (r / cNW) * cNF + cN0 + (r % cNW);
        float* cRow = C + (size_t)crow * cPitch;
        #pragma unroll
        for (int ni = 0; ni < 4; ni++) {
            int col = colBase + tx * 4 + ni;
            if (col >= N) continue;
            float v = acc[mi][ni] + bias[col];
            if (addRes) cRow[col] += v; else cRow[col] = v;
        }
    }
}

// ------------------------- bf16 tensor-core GEMM ---------------------------
#define HSMEM (2 * 128 * 128 * 2)

__global__ void __launch_bounds__(256) hgemm(
    const float* __restrict__ A, int aN0, int aNW, int aNF,
    const float* __restrict__ B, const float* __restrict__ bias,
    float* __restrict__ C, int cN0, int cNW, int cNF, int cPitch,
    int addRes)
{
    extern __shared__ __nv_bfloat16 hsm[];
    __nv_bfloat16* As = hsm;
    __nv_bfloat16* Bs = hsm + 128*128;

    int tid = threadIdx.x;
    int rowBase = blockIdx.y * 128;
    int colBase = blockIdx.x * 128;

    int lr = tid >> 1, lkh = tid & 1;
    {
        int ar = rowBase + lr;
        int arow = (ar / aNW) * aNF + aN0 + (ar % aNW);
        const float* ap = A + (size_t)arow * 128 + lkh * 64;
        const float* bp = B + (size_t)(colBase + lr) * 128 + lkh * 64;
        int sw = lr & 7;
        #pragma unroll
        for (int j = 0; j < 8; j++) {
            int c = lkh * 8 + j;
            int cp = c ^ sw;
            float4 v0 = *(const float4*)(ap + j * 8);
            float4 v1 = *(const float4*)(ap + j * 8 + 4);
            uint4 u;
            u.x = pack_bf2(v0.x, v0.y); u.y = pack_bf2(v0.z, v0.w);
            u.z = pack_bf2(v1.x, v1.y); u.w = pack_bf2(v1.z, v1.w);
            *(uint4*)&As[lr * 128 + cp * 8] = u;
            v0 = *(const float4*)(bp + j * 8);
            v1 = *(const float4*)(bp + j * 8 + 4);
            u.x = pack_bf2(v0.x, v0.y); u.y = pack_bf2(v0.z, v0.w);
            u.z = pack_bf2(v1.x, v1.y); u.w = pack_bf2(v1.z, v1.w);
            *(uint4*)&Bs[lr * 128 + cp * 8] = u;
        }
    }
    __syncthreads();

    int wid = tid >> 5, lane = tid & 31;
    int wm = (wid & 3) * 32;
    int wn = (wid >> 2) * 64;
    int g = lane >> 2, tg = lane & 3;

    float acc[2][8][4];
    #pragma unroll
    for (int mt = 0; mt < 2; mt++)
        #pragma unroll
        for (int nt = 0; nt < 8; nt++)
            #pragma unroll
            for (int q = 0; q < 4; q++) acc[mt][nt][q] = 0.f;

    unsigned asBase = (unsigned)__cvta_generic_to_shared(As);
    unsigned bsBase = (unsigned)__cvta_generic_to_shared(Bs);

    #pragma unroll
    for (int ks = 0; ks < 8; ks++) {
        int c0 = ks * 2;
        unsigned afr[2][4];
        #pragma unroll
        for (int mt = 0; mt < 2; mt++) {
            int row = wm + mt * 16 + (lane & 15);
            int ch = c0 + (lane >> 4);
            unsigned addr = asBase + (unsigned)((row * 128 + ((ch ^ (row & 7)) << 3)) * 2);
            ldm4(afr[mt][0], afr[mt][1], afr[mt][2], afr[mt][3], addr);
        }
        unsigned bfr[8][2];
        #pragma unroll
        for (int p = 0; p < 4; p++) {
            int row = wn + p * 16 + (lane & 7) + ((lane >> 4) << 3);
            int ch = c0 + ((lane >> 3) & 1);
            unsigned addr = bsBase + (unsigned)((row * 128 + ((ch ^ (row & 7)) << 3)) * 2);
            unsigned r0, r1, r2, r3;
            ldm4(r0, r1, r2, r3, addr);
            bfr[p * 2][0] = r0;     bfr[p * 2][1] = r1;
            bfr[p * 2 + 1][0] = r2; bfr[p * 2 + 1][1] = r3;
        }
        #pragma unroll
        for (int mt = 0; mt < 2; mt++)
            #pragma unroll
            for (int nt = 0; nt < 8; nt++)
                mma_bf16(acc[mt][nt], afr[mt], bfr[nt][0], bfr[nt][1]);
    }

    #pragma unroll
    for (int mt = 0; mt < 2; mt++) {
        int r0g = rowBase + wm + mt * 16 + g;
        #pragma unroll
        for (int half = 0; half < 2; half++) {
            int r = r0g + half * 8;
            int crow = (r / cNW) * cNF + cN0 + (r % cNW);
            float* cRow = C + (size_t)crow * cPitch;
            #pragma unroll
            for (int nt = 0; nt < 8; nt++) {
                int col = colBase + wn + nt * 8 + 2 * tg;
                float2 b2 = *(const float2*)(bias + col);
                float vx = acc[mt][nt][half * 2 + 0] + b2.x;
                float vy = acc[mt][nt][half * 2 + 1] + b2.y;
                if (addRes) {
                    float2 old = *(const float2*)(cRow + col);
                    vx += old.x; vy += old.y;
                }
                float2 o2; o2.x = vx; o2.y = vy;
                *(float2*)(cRow + col) = o2;
            }
        }
    }
}

// ------------------------- bf16 mma attention -------------------------------
// Block = (n, e, half: rows i in [i0, i0+96)). 256 threads = 8 warps.
// S[il][j] = QK[il][j] + Z1s[il][j] + Z2s[j][il]
//   Z1s[il][j] = (Q@PK^T)[il][d],  Z2s[j][il] = (K@PQ^T)[j][d],
//   d = dlo + t;  DSIGN=+1: j = t+il-95;  DSIGN=-1: j = 191+il-t.
// smem (bytes): Qs@0 (96x40 bf16), Ks@7680 (192x40), PKs@23040 (288x40),
//   PQs@46080 (288x40; Vt 32x200 bf16 overlays), Z1s@69120 (96x196 f32, reused
//   as packed-bf16 P), Z2s@144384 (192x97 f32). Total 218880.
#define ATC_SMEM 218880

template<int DSIGN>
__global__ void __launch_bounds__(256, 1) attn_tc(
    const float* __restrict__ qPtr, int qPitch, int qOff,
    const float* __restrict__ kPtr, int kPitch, int kOff,
    const float* __restrict__ vPtr, int vPitch, int vOff,
    const float* __restrict__ proj, float* __restrict__ vo, int nB)
{
    extern __shared__ char smraw[];
    __nv_bfloat16* Qs  = (__nv_bfloat16*)(smraw);
    __nv_bfloat16* Ks  = (__nv_bfloat16*)(smraw + 7680);
    __nv_bfloat16* PKs = (__nv_bfloat16*)(smraw + 23040);
    __nv_bfloat16* PQs = (__nv_bfloat16*)(smraw + 46080);
    __nv_bfloat16* Vt  = PQs;                       // overlay (after Z2 phase)
    float* Z1s = (float*)(smraw + 69120);
    float* Z2s = (float*)(smraw + 144384);

    int n = blockIdx.x, e = blockIdx.y;
    int i0 = blockIdx.z * 96;
    int tid = threadIdx.x;
    const float scale = 0.17677669529663687f;
    const int dlo = (DSIGN > 0) ? (96 - i0) : i0;

    // ---- loads: Q (scaled), K, PK, PQ (scaled) ----
    for (int idx = tid; idx < 96 * 8; idx += 256) {
        int r = idx >> 3, c4 = (idx & 7) * 4;
        float4 v = *(const float4*)(qPtr + (size_t)((i0 + r) * nB + n) * qPitch + qOff + e * 32 + c4);
        *(uint2*)&Qs[r * 40 + c4] = pack4s(v, scale);
    }
    for (int idx = tid; idx < 192 * 8; idx += 256) {
        int r = idx >> 3, c4 = (idx & 7) * 4;
        float4 v = *(const float4*)(kPtr + (size_t)(r * nB + n) * kPitch + kOff + e * 32 + c4);
        *(uint2*)&Ks[r * 40 + c4] = pack4(v);
    }
    for (int idx = tid; idx < 288 * 8; idx += 256) {
        int t = idx >> 3, c4 = (idx & 7) * 4;
        int d = dlo + t;
        float4 vk = make_float4(0, 0, 0, 0), vq = make_float4(0, 0, 0, 0);
        if (d < 383) {
            vk = *(const float4*)(proj + (size_t)d * 256 + 128 + e * 32 + c4);
            vq = *(const float4*)(proj + (size_t)d * 256 + e * 32 + c4);
        }
        *(uint2*)&PKs[t * 40 + c4] = pack4(vk);
        *(uint2*)&PQs[t * 40 + c4] = pack4s(vq, scale);
    }
    __syncthreads();

    int wid = tid >> 5, lane = tid & 31;
    int g = lane >> 2, tg = lane & 3;
    unsigned qBase  = (unsigned)__cvta_generic_to_shared(Qs);
    unsigned kBase  = (unsigned)__cvta_generic_to_shared(Ks);
    unsigned pkBase = (unsigned)__cvta_generic_to_shared(PKs);
    unsigned pqBase = (unsigned)__cvta_generic_to_shared(PQs);
    unsigned vtBase = (unsigned)__cvta_generic_to_shared(Vt);
    unsigned pBase  = (unsigned)__cvta_generic_to_shared(Z1s);

    // ---- Z1 = Q @ PK^T, skew-scattered: 6 m-tiles x 13 n16-tiles ----
    #pragma unroll 1
    for (int u = wid; u < 78; u += 8) {
        int mt = u / 13, nt = u % 13;
        int t0m = (DSIGN > 0) ? (80 - 16 * mt) : (16 * mt);
        int tb = t0m + nt * 16;
        unsigned a[2][4], b[2][4];
        #pragma unroll
        for (int ks = 0; ks < 2; ks++) {
            unsigned addrA = qBase + (unsigned)((mt * 16 + (lane & 15)) * 80 + (ks * 2 + (lane >> 4)) * 16);
            ldm4(a[ks][0], a[ks][1], a[ks][2], a[ks][3], addrA);
            int row = tb + (lane & 7) + ((lane >> 4) << 3);
            unsigned addrB = pkBase + (unsigned)(row * 80 + (ks * 2 + ((lane >> 3) & 1)) * 16);
            ldm4(b[ks][0], b[ks][1], b[ks][2], b[ks][3], addrB);
        }
        float acc[2][4];
        #pragma unroll
        for (int h = 0; h < 2; h++) { acc[h][0] = acc[h][1] = acc[h][2] = acc[h][3] = 0.f; }
        mma_bf16(acc[0], a[0], b[0][0], b[0][1]); mma_bf16(acc[0], a[1], b[1][0], b[1][1]);
        mma_bf16(acc[1], a[0], b[0][2], b[0][3]); mma_bf16(acc[1], a[1], b[1][2], b[1][3]);
        #pragma unroll
        for (int h = 0; h < 2; h++) {
            int t = tb + h * 8 + 2 * tg;
            #pragma unroll
            for (int rr = 0; rr < 2; rr++) {
                int il = mt * 16 + g + 8 * rr;
                int j0 = (DSIGN > 0) ? (t + il - 95) : (191 + il - t);
                int j1 = (DSIGN > 0) ? (j0 + 1) : (j0 - 1);
                if ((unsigned)j0 < 192u) Z1s[il * 196 + j0] = acc[h][rr * 2 + 0];
                if ((unsigned)j1 < 192u) Z1s[il * 196 + j1] = acc[h][rr * 2 + 1];
            }
        }
    }

    // ---- Z2 = K @ PQ^T, skew-scattered: 12 m-tiles x 7 n16-tiles ----
    #pragma unroll 1
    for (int u = wid; u < 84; u += 8) {
        int jt = u / 7, nt = u % 7;
        int t0m = (DSIGN > 0) ? (16 * jt) : (176 - 16 * jt);
        int tb = t0m + nt * 16;
        unsigned a[2][4], b[2][4];
        #pragma unroll
        for (int ks = 0; ks < 2; ks++) {
            unsigned addrA = kBase + (unsigned)((jt * 16 + (lane & 15)) * 80 + (ks * 2 + (lane >> 4)) * 16);
            ldm4(a[ks][0], a[ks][1], a[ks][2], a[ks][3], addrA);
            int row = tb + (lane & 7) + ((lane >> 4) << 3);
            unsigned addrB = pqBase + (unsigned)(row * 80 + (ks * 2 + ((lane >> 3) & 1)) * 16);
            ldm4(b[ks][0], b[ks][1], b[ks][2], b[ks][3], addrB);
        }
        float acc[2][4];
        #pragma unroll
        for (int h = 0; h < 2; h++) { acc[h][0] = acc[h][1] = acc[h][2] = acc[h][3] = 0.f; }
        mma_bf16(acc[0], a[0], b[0][0], b[0][1]); mma_bf16(acc[0], a[1], b[1][0], b[1][1]);
        mma_bf16(acc[1], a[0], b[0][2], b[0][3]); mma_bf16(acc[1], a[1], b[1][2], b[1][3]);
        #pragma unroll
        for (int h = 0; h < 2; h++) {
            int t = tb + h * 8 + 2 * tg;
            #pragma unroll
            for (int rr = 0; rr < 2; rr++) {
                int j = jt * 16 + g + 8 * rr;
                int il0 = (DSIGN > 0) ? (j + 95 - t) : (j + t - 191);
                int il1 = (DSIGN > 0) ? (il0 - 1) : (il0 + 1);
                if ((unsigned)il0 < 96u) Z2s[j * 97 + il0] = acc[h][rr * 2 + 0];
                if ((unsigned)il1 < 96u) Z2s[j * 97 + il1] = acc[h][rr * 2 + 1];
            }
        }
    }
    __syncthreads();

    // ---- warps 0-5: QK^T + gather + softmax. warps 6-7: load Vt ----
    float acc[24][4];
    float invA = 0.f, invB = 0.f;
    if (wid < 6) {
        #pragma unroll
        for (int nt = 0; nt < 24; nt++)
            #pragma unroll
            for (int q = 0; q < 4; q++) acc[nt][q] = 0.f;

        unsigned a[2][4];
        #pragma unroll
        for (int ks = 0; ks < 2; ks++) {
            unsigned addrA = qBase + (unsigned)((wid * 16 + (lane & 15)) * 80 + (ks * 2 + (lane >> 4)) * 16);
            ldm4(a[ks][0], a[ks][1], a[ks][2], a[ks][3], addrA);
        }
        #pragma unroll
        for (int nt16 = 0; nt16 < 12; nt16++) {
            unsigned b[2][4];
            #pragma unroll
            for (int ks = 0; ks < 2; ks++) {
                int row = nt16 * 16 + (lane & 7) + ((lane >> 4) << 3);
                unsigned addrB = kBase + (unsigned)(row * 80 + (ks * 2 + ((lane >> 3) & 1)) * 16);
                ldm4(b[ks][0], b[ks][1], b[ks][2], b[ks][3], addrB);
            }
            mma_bf16(acc[nt16 * 2],     a[0], b[0][0], b[0][1]);
            mma_bf16(acc[nt16 * 2],     a[1], b[1][0], b[1][1]);
            mma_bf16(acc[nt16 * 2 + 1], a[0], b[0][2], b[0][3]);
            mma_bf16(acc[nt16 * 2 + 1], a[1], b[1][2], b[1][3]);
        }

        int ilA = wid * 16 + g, ilB = ilA + 8;
        #pragma unroll
        for (int nt = 0; nt < 24; nt++) {
            int j = nt * 8 + 2 * tg;
            acc[nt][0] += Z1s[ilA * 196 + j]     + Z2s[j * 97 + ilA];
            acc[nt][1] += Z1s[ilA * 196 + j + 1] + Z2s[(j + 1) * 97 + ilA];
            acc[nt][2] += Z1s[ilB * 196 + j]     + Z2s[j * 97 + ilB];
            acc[nt][3] += Z1s[ilB * 196 + j + 1] + Z2s[(j + 1) * 97 + ilB];
        }

        float mA = -1e30f, mB = -1e30f;
        #pragma unroll
        for (int nt = 0; nt < 24; nt++) {
            mA = fmaxf(mA, fmaxf(acc[nt][0], acc[nt][1]));
            mB = fmaxf(mB, fmaxf(acc[nt][2], acc[nt][3]));
        }
        mA = fmaxf(mA, __shfl_xor_sync(0xffffffffu, mA, 1));
        mA = fmaxf(mA, __shfl_xor_sync(0xffffffffu, mA, 2));
        mB = fmaxf(mB, __shfl_xor_sync(0xffffffffu, mB, 1));
        mB = fmaxf(mB, __shfl_xor_sync(0xffffffffu, mB, 2));
        float sA = 0.f, sB = 0.f;
        #pragma unroll
        for (int nt = 0; nt < 24; nt++) {
            acc[nt][0] = __expf(acc[nt][0] - mA); sA += acc[nt][0];
            acc[nt][1] = __expf(acc[nt][1] - mA); sA += acc[nt][1];
            acc[nt][2] = __expf(acc[nt][2] - mB); sB += acc[nt][2];
            acc[nt][3] = __expf(acc[nt][3] - mB); sB += acc[nt][3];
        }
        sA += __shfl_xor_sync(0xffffffffu, sA, 1);
        sA += __shfl_xor_sync(0xffffffffu, sA, 2);
        sB += __shfl_xor_sync(0xffffffffu, sB, 1);
        sB += __shfl_xor_sync(0xffffffffu, sB, 2);
        invA = 1.f / sA; invB = 1.f / sB;
    } else {
        // load Vt[c][j] = V[j][c] into the (dead) PQs region
        for (int idx = tid - 192; idx < 192 * 8; idx += 64) {
            int j = idx >> 3, c4 = (idx & 7) * 4;
            float4 v = *(const float4*)(vPtr + (size_t)(j * nB + n) * vPitch + vOff + e * 32 + c4);
            Vt[(c4 + 0) * 200 + j] = __float2bfloat16(v.x);
            Vt[(c4 + 1) * 200 + j] = __float2bfloat16(v.y);
            Vt[(c4 + 2) * 200 + j] = __float2bfloat16(v.z);
            Vt[(c4 + 3) * 200 + j] = __float2bfloat16(v.w);
        }
    }
    __syncthreads();

    // ---- write normalized P as packed bf16 into the Z1s region ----
    if (wid < 6) {
        unsigned* Pw = (unsigned*)Z1s;
        int ilA = wid * 16 + g, ilB = ilA + 8;
        #pragma unroll
        for (int nt = 0; nt < 24; nt++) {
            Pw[ilA * 196 + nt * 4 + tg] = pack_bf2(acc[nt][0] * invA, acc[nt][1] * invA);
            Pw[ilB * 196 + nt * 4 + tg] = pack_bf2(acc[nt][2] * invB, acc[nt][3] * invB);
        }
    }
    __syncthreads();

    // ---- O = P @ V : warps 0-5, m-tile = wid ----
    if (wid < 6) {
        float oacc[4][4];
        #pragma unroll
        for (int t = 0; t < 4; t++)
            #pragma unroll
            for (int q = 0; q < 4; q++) oacc[t][q] = 0.f;

        #pragma unroll 1
        for (int ks = 0; ks < 12; ks++) {
            unsigned a[4];
            unsigned addrA = pBase + (unsigned)((wid * 16 + (lane & 15)) * 784 + (ks * 2 + (lane >> 4)) * 16);
            ldm4(a[0], a[1], a[2], a[3], addrA);
            #pragma unroll
            for (int nb = 0; nb < 2; nb++) {
                int row = nb * 16 + (lane & 7) + ((lane >> 4) << 3);
                unsigned addrB = vtBase + (unsigned)(row * 400 + (ks * 2 + ((lane >> 3) & 1)) * 16);
                unsigned b0, b1, b2, b3;
                ldm4(b0, b1, b2, b3, addrB);
                mma_bf16(oacc[nb * 2],     a, b0, b1);
                mma_bf16(oacc[nb * 2 + 1], a, b2, b3);
            }
        }

        int iA = i0 + wid * 16 + g, iB = iA + 8;
        size_t oA = (size_t)(iA * nB + n) * 128 + e * 32;
        size_t oB = (size_t)(iB * nB + n) * 128 + e * 32;
        #pragma unroll
        for (int t = 0; t < 4; t++) {
            int c = t * 8 + 2 * tg;
            float2 vA; vA.x = oacc[t][0]; vA.y = oacc[t][1];
            float2 vB; vB.x = oacc[t][2]; vB.y = oacc[t][3];
            *(float2*)(vo + oA + c) = vA;
            *(float2*)(vo + oB + c) = vB;
        }
    }
}

// ---------------------------------------------------------------------------
extern "C" void kernel_launch(void* const* d_in, const int* in_sizes, int n_in,
                              void* d_out, int out_size)
{
    (void)in_sizes; (void)n_in; (void)out_size;
    const float* feat_left  = (const float*)d_in[0];
    const float* feat_right = (const float*)d_in[1];
    const float* pos_enc    = (const float*)d_in[2];
    const float* s_iw = (const float*)d_in[3];
    const float* s_ib = (const float*)d_in[4];
    const float* s_ow = (const float*)d_in[5];
    const float* s_ob = (const float*)d_in[6];
    const float* s_g  = (const float*)d_in[7];
    const float* s_b  = (const float*)d_in[8];
    const float* c_iw = (const float*)d_in[9];
    const float* c_ib = (const float*)d_in[10];
    const float* c_ow = (const float*)d_in[11];
    const float* c_ob = (const float*)d_in[12];
    const float* c_g1 = (const float*)d_in[13];
    const float* c_b1 = (const float*)d_in[14];
    const float* c_g2 = (const float*)d_in[15];
    const float* c_b2 = (const float*)d_in[16];

    float* feat = (float*)d_out;

    float *ln_buf, *ln2_buf, *qkv, *vo, *projb;
    cudaGetSymbolAddress((void**)&ln_buf, g_ln);
    cudaGetSymbolAddress((void**)&ln2_buf, g_ln2);
    cudaGetSymbolAddress((void**)&qkv, g_qkv);
    cudaGetSymbolAddress((void**)&vo, g_vo);
    cudaGetSymbolAddress((void**)&projb, g_proj);
    float* projS = projb;
    float* projC = projb + 383 * 256;
    float* qb  = qkv;
    float* kvb = qkv + 192 * 128 * 128;

    cudaFuncSetAttribute(attn_tc<1>,  cudaFuncAttributeMaxDynamicSharedMemorySize, ATC_SMEM);
    cudaFuncSetAttribute(attn_tc<-1>, cudaFuncAttributeMaxDynamicSharedMemorySize, ATC_SMEM);
    cudaFuncSetAttribute(hgemm, cudaFuncAttributeMaxDynamicSharedMemorySize, HSMEM);

    build_feat<<<dim3(6, 4, 256), dim3(32, 32)>>>(feat_left, feat_right, feat);

    for (int L = 0; L < 4; L++) {
        const float* siw = s_iw + (size_t)L * 384 * 128;
        const float* sib = s_ib + (size_t)L * 384;
        const float* sow = s_ow + (size_t)L * 128 * 128;
        const float* sob = s_ob + (size_t)L * 128;
        const float* ciw = c_iw + (size_t)L * 384 * 128;
        const float* cib = c_ib + (size_t)L * 384;
        const float* cow = c_ow + (size_t)L * 128 * 128;
        const float* cob = c_ob + (size_t)L * 128;

        // ---------------- self-attention ----------------
        ln4_kernel<<<12288, 128>>>(feat, 0, 256, 256, s_g + L * 128, s_b + L * 128, ln_buf);
        sgemm64<<<dim3(4, 6), 256>>>(pos_enc, 0, 383, 383, siw, sib,
                                     projS, 0, 383, 383, 256, 383, 256, 0);
        hgemm<<<dim3(3, 384), 256, HSMEM>>>(ln_buf, 0, 256, 256, siw, sib,
                                            qkv, 0, 256, 256, 384, 0);
        attn_tc<1><<<dim3(256, 4, 2), 256, ATC_SMEM>>>(qkv, 384, 0, qkv, 384, 128,
                                                       qkv, 384, 256, projS, vo, 256);
        hgemm<<<dim3(1, 384), 256, HSMEM>>>(vo, 0, 256, 256, sow, sob,
                                            feat, 0, 256, 256, 128, 1);

        // ---------------- cross-attention ----------------
        ln4_kernel<<<12288, 128>>>(feat, 0, 256, 256, c_g1 + L * 128, c_b1 + L * 128, ln_buf);
        sgemm64<<<dim3(4, 6), 256>>>(pos_enc, 0, 383, 383, ciw, cib,
                                     projC, 0, 383, 383, 256, 383, 256, 0);

        // fr update: q from fr2, kv from fl2, flipped table (DSIGN=-1)
        hgemm<<<dim3(1, 192), 256, HSMEM>>>(ln_buf, 128, 128, 256, ciw, cib,
                                            qb, 0, 128, 128, 128, 0);
        hgemm<<<dim3(2, 192), 256, HSMEM>>>(ln_buf, 0, 128, 256, ciw + 128 * 128, cib + 128,
                                            kvb, 0, 128, 128, 256, 0);
        attn_tc<-1><<<dim3(128, 4, 2), 256, ATC_SMEM>>>(qb, 128, 0, kvb, 256, 0,
                                                        kvb, 256, 128, projC, vo, 128);
        hgemm<<<dim3(1, 192), 256, HSMEM>>>(vo, 0, 128, 128, cow, cob,
                                            feat, 128, 128, 256, 128, 1);

        // fr2n = LN(updated fr)
        ln4_kernel<<<6144, 128>>>(feat, 128, 128, 256, c_g2 + L * 128, c_b2 + L * 128, ln2_buf);

        // fl update: q from fl2, kv from fr2n, normal table (DSIGN=+1)
        hgemm<<<dim3(1, 192), 256, HSMEM>>>(ln_buf, 0, 128, 256, ciw, cib,
                                            qb, 0, 128, 128, 128, 0);
        hgemm<<<dim3(2, 192), 256, HSMEM>>>(ln2_buf, 0, 128, 128, ciw + 128 * 128, cib + 128,
                                            kvb, 0, 128, 128, 256, 0);
        attn_tc<1><<<dim3(128, 4, 2), 256, ATC_SMEM>>>(qb, 128, 0, kvb, 256, 0,
                                                       kvb, 256, 128, projC, vo, 128);
        hgemm<<<dim3(1, 192), 256, HSMEM>>>(vo, 0, 128, 128, cow, cob,
                                            feat, 0, 128, 256, 128, 1);
    }
}